// round 11
// baseline (speedup 1.0000x reference)
#include <cuda_runtime.h>
#include <cstdint>

// Problem constants (fixed by the dataset)
#define BQ    128
#define TT    512
#define CC    1024
#define LL    64
#define SS    129           // 2*LL + 1 extended states
#define BLANKC 1023
#define EPSF  1e-7f
#define JPER  5             // states per lane (26 lanes * 5 = 130 >= 129)
#define RSTRIDE 68          // smem row stride in floats (66 used)
#define EF_TARGET 226       // rescale anchor: warp max near 2^99
#define NPROD 4             // producer warps
#define PD    8             // per-producer pending commit groups
#define RDYBIG 0x3fffffff

#define SMEM_BYTES (TT * RSTRIDE * 4)   // 139,264 B — full time axis resident

__device__ __forceinline__ void cpasync4(uint32_t saddr, const float* g) {
    asm volatile("cp.async.ca.shared.global [%0], [%1], 4;"
                 :: "r"(saddr), "l"(g) : "memory");
}
__device__ __forceinline__ void cpcommit() {
    asm volatile("cp.async.commit_group;" ::: "memory");
}
template <int N> __device__ __forceinline__ void cpwait() {
    asm volatile("cp.async.wait_group %0;" :: "n"(N) : "memory");
}
__device__ __forceinline__ void st_release_shared(uint32_t saddr, int v) {
    asm volatile("st.release.cta.shared.b32 [%0], %1;" :: "r"(saddr), "r"(v) : "memory");
}
__device__ __forceinline__ int ld_acquire_shared(uint32_t saddr) {
    int v;
    asm volatile("ld.acquire.cta.shared.b32 %0, [%1];" : "=r"(v) : "r"(saddr) : "memory");
    return v;
}

__device__ __forceinline__ float pick5(const float a0, const float a1, const float a2,
                                       const float a3, const float a4, int j) {
    float r = a0;
    if (j == 1) r = a1;
    else if (j == 2) r = a2;
    else if (j == 3) r = a3;
    else if (j == 4) r = a4;
    return r;
}

__global__ __launch_bounds__(32 * (NPROD + 1), 1)
void ctc_flat_kernel(const int* __restrict__ y_true,
                     const float* __restrict__ y_pred,
                     const int* __restrict__ input_length,
                     const int* __restrict__ label_length,
                     float* __restrict__ out)
{
    extern __shared__ float buf[];           // [TT][RSTRIDE] — whole time axis
    __shared__ int s_ready[NPROD];           // highest completed own-row per producer

    const int b    = blockIdx.x;
    const int tid  = threadIdx.x;
    const int warp = tid >> 5;
    const int lane = tid & 31;
    const unsigned FULL = 0xffffffffu;

    const int Tb = input_length[b];          // block-uniform, in [256, 512]
    const int Ll = label_length[b];
    const int Sb = 2 * Ll + 1;

    const int*   lrow = y_true + b * LL;
    const float* prow = y_pred + (size_t)b * TT * CC;
    const uint32_t smem_base = (uint32_t)__cvta_generic_to_shared(&buf[0]);
    const uint32_t rdy_base  = (uint32_t)__cvta_generic_to_shared(&s_ready[0]);

    if (tid < NPROD) s_ready[tid] = -1;
    // consumer-owned zero sink: slot 65 of every row (producers never touch it)
    if (warp == 0)
        for (int r = lane; r < TT; r += 32) buf[r * RSTRIDE + 65] = 0.0f;
    __syncthreads();

    if (warp >= 1) {
        // ===================== PRODUCER p: rows p, p+4, p+8, ... =====================
        const int p = warp - 1;
        const float* gbase0 = prow + lrow[lane];
        const float* gbase1 = prow + lrow[lane + 32];
        const float* gblank = prow + BLANKC;

        int i = 0;
        for (int r = p; r < Tb; r += NPROD, i++) {
            const uint32_t wa = smem_base + (uint32_t)(r * RSTRIDE + lane) * 4u;
            cpasync4(wa, gbase0 + (size_t)r * CC);
            cpasync4(wa + 128u, gbase1 + (size_t)r * CC);
            if (lane == 0)
                cpasync4(smem_base + (uint32_t)(r * RSTRIDE + 64) * 4u,
                         gblank + (size_t)r * CC);
            cpcommit();

            if (i >= PD) {
                cpwait<PD>();                        // own rows <= p + NPROD*(i-PD) done
                if (lane == 0)
                    st_release_shared(rdy_base + 4u * p, p + NPROD * (i - PD));
            }
        }
        cpwait<0>();
        if (lane == 0) st_release_shared(rdy_base + 4u * p, RDYBIG);
    } else {
        // ============================== CONSUMER ==============================
        int   off[JPER];     // 0..63 label, 64 blank, 65 zero sink (invalid)
        float skipf[JPER];
#pragma unroll
        for (int j = 0; j < JPER; j++) {
            const int s = lane * JPER + j;
            const bool v = (s < SS) && (s < Sb);
            int  o  = 65;
            bool sk = false;
            if (v) {
                if (s & 1) {
                    o = s >> 1;
                    if (s >= 3) sk = (lrow[o] != lrow[o - 1]);
                } else {
                    o = 64;
                }
            }
            off[j]   = o;
            skipf[j] = sk ? 1.0f : 0.0f;
        }

        float a0 = 0.f, a1r = 0.f, a2r = 0.f, a3r = 0.f, a4r = 0.f;
        if (lane == 0) a0 = 1.0f;

        // wait for row 0
        while (min(min(ld_acquire_shared(rdy_base),      ld_acquire_shared(rdy_base + 4)),
                   min(ld_acquire_shared(rdy_base + 8),  ld_acquire_shared(rdy_base + 12))) < 0) {}

        float ee[2][JPER];
#pragma unroll
        for (int j = 0; j < JPER; j++) ee[0][j] = buf[off[j]] + EPSF;

        int esum = 0;        // exact power-of-two rescale accumulator
        const int NG = (Tb + 3) >> 2;            // 4-step groups

        for (int i = 0; i < NG; i++) {
            // rows needed this group: up to min(4i+4, Tb-1)
            {
                int tgt = 4 * i + 4;
                if (tgt > Tb - 1) tgt = Tb - 1;
                while (min(min(ld_acquire_shared(rdy_base),      ld_acquire_shared(rdy_base + 4)),
                           min(ld_acquire_shared(rdy_base + 8),  ld_acquire_shared(rdy_base + 12))) < tgt) {}
            }

#pragma unroll
            for (int k = 0; k < 4; k++) {
                const int t   = 4 * i + k;
                const int cur = t & 1;
                const int nxt = cur ^ 1;

                // raw emissions for step t+1 (clamped to last written row)
                const int tn = (t + 1 < Tb) ? (t + 1) : (Tb - 1);
                const float* rr = &buf[tn * RSTRIDE];
                const float r0 = rr[off[0]], r1 = rr[off[1]], r2 = rr[off[2]],
                            r3 = rr[off[3]], r4 = rr[off[4]];

                if (t < Tb) {
                    float h3 = __shfl_up_sync(FULL, a3r, 1);
                    float h4 = __shfl_up_sync(FULL, a4r, 1);
                    if (lane == 0) { h3 = 0.f; h4 = 0.f; }

                    const float n0 = (a0  + h4  + skipf[0] * h3 ) * ee[cur][0];
                    const float n1 = (a1r + a0  + skipf[1] * h4 ) * ee[cur][1];
                    const float n2 = (a2r + a1r + skipf[2] * a0 ) * ee[cur][2];
                    const float n3 = (a3r + a2r + skipf[3] * a1r) * ee[cur][3];
                    const float n4 = (a4r + a3r + skipf[4] * a2r) * ee[cur][4];
                    a0 = n0; a1r = n1; a2r = n2; a3r = n3; a4r = n4;
                }

                ee[nxt][0] = r0 + EPSF;
                ee[nxt][1] = r1 + EPSF;
                ee[nxt][2] = r2 + EPSF;
                ee[nxt][3] = r3 + EPSF;
                ee[nxt][4] = r4 + EPSF;

                // exact power-of-two rescale every 4 steps (anchor ~2^99)
                if (k == 3 && t < Tb) {
                    float m = fmaxf(fmaxf(fmaxf(a0, a1r), fmaxf(a2r, a3r)), a4r);
                    unsigned mu = __reduce_max_sync(FULL, __float_as_uint(m));
                    if (mu != 0u) {
                        const int ef = (int)(mu >> 23);
                        int kk = EF_TARGET - ef;
                        kk = kk > 127 ? 127 : (kk < -126 ? -126 : kk);
                        const float sc = __int_as_float((unsigned)(127 + kk) << 23);
                        esum -= kk;
                        a0 *= sc; a1r *= sc; a2r *= sc; a3r *= sc; a4r *= sc;
                    }
                }
            }
        }

        // loss = -( log(alpha[2Ll] + alpha[2Ll-1]) + esum*ln2 )
        const int se0 = 2 * Ll;
        const int se1 = 2 * Ll - 1;
        const int l0 = se0 / JPER, j0 = se0 % JPER;
        const int l1 = se1 / JPER, j1 = se1 % JPER;

        const float v0 = pick5(a0, a1r, a2r, a3r, a4r, j0);
        const float v1 = pick5(a0, a1r, a2r, a3r, a4r, j1);
        const float fa1 = __shfl_sync(FULL, v0, l0);
        const float fa2 = __shfl_sync(FULL, v1, l1);

        if (lane == 0) {
            const float s = fmaxf(fa1 + fa2, 1e-43f);
            out[b] = -(logf(s) + (float)esum * 0.6931471805599453f);
        }
    }
}

extern "C" void kernel_launch(void* const* d_in, const int* in_sizes, int n_in,
                              void* d_out, int out_size)
{
    const int*   y_true       = (const int*)  d_in[0];   // [B,L] int32
    const float* y_pred       = (const float*)d_in[1];   // [B,T,C] f32
    const int*   input_length = (const int*)  d_in[2];   // [B,1] int32
    const int*   label_length = (const int*)  d_in[3];   // [B,1] int32
    float*       out          = (float*)d_out;           // [B,1] f32

    cudaFuncSetAttribute(ctc_flat_kernel,
                         cudaFuncAttributeMaxDynamicSharedMemorySize, SMEM_BYTES);
    ctc_flat_kernel<<<BQ, 32 * (NPROD + 1), SMEM_BYTES>>>(
        y_true, y_pred, input_length, label_length, out);
}

// round 12
// speedup vs baseline: 1.0655x; 1.0655x over previous
#include <cuda_runtime.h>
#include <cstdint>

// Problem constants (fixed by the dataset)
#define BQ    128
#define TT    512
#define CC    1024
#define LL    64
#define SS    129           // 2*LL + 1 extended states
#define BLANKC 1023
#define EPSF  1e-7f
#define JPER  5             // states per lane (26 lanes * 5 = 130 >= 129)
#define DEPTH 32            // smem ring rows (power of two)
#define WAITN 16            // wait_group depth: 17 pending groups ~ 51 LDGSTS
#define RSTRIDE 68          // ring row stride in floats (66 used)
#define EF_TARGET 226       // rescale anchor: warp max near 2^99

__device__ __forceinline__ void cpasync4(uint32_t saddr, const float* g) {
    asm volatile("cp.async.ca.shared.global [%0], [%1], 4;"
                 :: "r"(saddr), "l"(g) : "memory");
}
__device__ __forceinline__ void cpcommit() {
    asm volatile("cp.async.commit_group;" ::: "memory");
}
template <int N> __device__ __forceinline__ void cpwait() {
    asm volatile("cp.async.wait_group %0;" :: "n"(N) : "memory");
}

__device__ __forceinline__ float pick5(const float a0, const float a1, const float a2,
                                       const float a3, const float a4, int j) {
    float r = a0;
    if (j == 1) r = a1;
    else if (j == 2) r = a2;
    else if (j == 3) r = a3;
    else if (j == 4) r = a4;
    return r;
}

__global__ __launch_bounds__(32, 1)
void ctc_fused_kernel(const int* __restrict__ y_true,
                      const float* __restrict__ y_pred,
                      const int* __restrict__ input_length,
                      const int* __restrict__ label_length,
                      float* __restrict__ out)
{
    __shared__ float ring[DEPTH][RSTRIDE];

    const int b    = blockIdx.x;
    const int lane = threadIdx.x;
    const unsigned FULL = 0xffffffffu;

    const int Tb = input_length[b];          // warp-uniform, in [256, 512]
    const int Ll = label_length[b];
    const int Sb = 2 * Ll + 1;

    const int*   lrow = y_true + b * LL;
    const float* prow = y_pred + (size_t)b * TT * CC;

    // Per-lane incremental gather pointers (advance by one row = CC floats)
    const float* g0 = prow + lrow[lane];          // label class  lane
    const float* g1 = prow + lrow[lane + 32];     // label class  lane+32
    const float* gb = prow + BLANKC;              // blank (only lane 0 issues)

    const uint32_t smem_base = (uint32_t)__cvta_generic_to_shared(&ring[0][0]);

    // Zero the sink slot (65) of every ring row once; cp.async never writes it.
    // Invalid states read it -> ee = EPS; contamination only flows rightward
    // into invalid territory, never back into valid states.
    for (int r = lane; r < DEPTH; r += 32) ring[r][65] = 0.0f;

    // Per-lane static state metadata: states s = lane*5 + j
    int   off[JPER];     // compact-row index: s>>1 label, 64 blank, 65 zero sink
    float skipf[JPER];
#pragma unroll
    for (int j = 0; j < JPER; j++) {
        const int s = lane * JPER + j;
        const bool v = (s < SS) && (s < Sb);
        int  o  = 65;
        bool sk = false;
        if (v) {
            if (s & 1) {
                o = s >> 1;
                if (s >= 3) sk = (lrow[o] != lrow[o - 1]);
            } else {
                o = 64;
            }
        }
        off[j]   = o;
        skipf[j] = sk ? 1.0f : 0.0f;
    }

    // ---- prologue: rows 0..DEPTH-1 (Tb >= 256 > DEPTH), one commit per row ----
#pragma unroll
    for (int r = 0; r < DEPTH; r++) {
        const uint32_t wa = smem_base + (uint32_t)(r * RSTRIDE + lane) * 4u;
        cpasync4(wa, g0);
        cpasync4(wa + 128u, g1);
        if (lane == 0)
            cpasync4(smem_base + (uint32_t)(r * RSTRIDE + 64) * 4u, gb);
        cpcommit();
        g0 += CC; g1 += CC; gb += CC;
    }
    cpwait<WAITN>();                 // rows 0..(DEPTH-1-WAITN) resident; row 0 ready

    // alpha init: linear domain, mass 1 at s=0
    float a0 = 0.f, a1r = 0.f, a2r = 0.f, a3r = 0.f, a4r = 0.f;
    if (lane == 0) a0 = 1.0f;

    // ee[parity][j]: emissions (p + EPS) for current / next step
    float ee[2][JPER];
#pragma unroll
    for (int j = 0; j < JPER; j++) ee[0][j] = ring[0][off[j]] + EPSF;

    int esum = 0;   // exact power-of-two rescale accumulator
                    // invariant: alpha_true = alpha_stored * 2^esum

    for (int tb = 0; tb < Tb; tb += 4) {
#pragma unroll
        for (int k = 0; k < 4; k++) {
            const int t   = tb + k;
            const int cur = t & 1;
            const int nxt = cur ^ 1;

            // 1) issue prefetch for row t+DEPTH (only while < Tb); ALWAYS commit
            //    so the group counter keeps advancing for wait<WAITN>.
            {
                const int tp = t + DEPTH;
                if (tp < Tb) {
                    const uint32_t wa = smem_base
                        + (uint32_t)((tp & (DEPTH - 1)) * RSTRIDE + lane) * 4u;
                    cpasync4(wa, g0);
                    cpasync4(wa + 128u, g1);
                    if (lane == 0)
                        cpasync4(smem_base + (uint32_t)((tp & (DEPTH - 1)) * RSTRIDE + 64) * 4u, gb);
                }
                cpcommit();
                g0 += CC; g1 += CC; gb += CC;
            }

            // 2) alpha recurrence for step t — independent of the pending wait,
            //    runs while the group drains.
            if (t < Tb) {
                float h3 = __shfl_up_sync(FULL, a3r, 1);
                float h4 = __shfl_up_sync(FULL, a4r, 1);
                if (lane == 0) { h3 = 0.f; h4 = 0.f; }

                const float n0 = (a0  + h4  + skipf[0] * h3 ) * ee[cur][0];
                const float n1 = (a1r + a0  + skipf[1] * h4 ) * ee[cur][1];
                const float n2 = (a2r + a1r + skipf[2] * a0 ) * ee[cur][2];
                const float n3 = (a3r + a2r + skipf[3] * a1r) * ee[cur][3];
                const float n4 = (a4r + a3r + skipf[4] * a2r) * ee[cur][4];
                a0 = n0; a1r = n1; a2r = n2; a3r = n3; a4r = n4;
            }

            // 3) completion through row >= t+1, then read raw emissions for t+1.
            //    (committed = DEPTH + t + 1 groups; wait<16> -> rows <= t+15 done)
            cpwait<WAITN>();
            {
                const float* rr = &ring[(t + 1) & (DEPTH - 1)][0];
                const float r0 = rr[off[0]], r1 = rr[off[1]], r2 = rr[off[2]],
                            r3 = rr[off[3]], r4 = rr[off[4]];
                // stale data past Tb-1 only feeds steps that are guarded off
                ee[nxt][0] = r0 + EPSF;
                ee[nxt][1] = r1 + EPSF;
                ee[nxt][2] = r2 + EPSF;
                ee[nxt][3] = r3 + EPSF;
                ee[nxt][4] = r4 + EPSF;
            }

            // 4) exact power-of-two rescale every 4 steps (anchor ~2^99)
            if (k == 3 && t < Tb) {
                float m = fmaxf(fmaxf(fmaxf(a0, a1r), fmaxf(a2r, a3r)), a4r);
                unsigned mu = __reduce_max_sync(FULL, __float_as_uint(m));
                if (mu != 0u) {
                    const int ef = (int)(mu >> 23);
                    int kk = EF_TARGET - ef;
                    kk = kk > 127 ? 127 : (kk < -126 ? -126 : kk);
                    const float sc = __int_as_float((unsigned)(127 + kk) << 23); // 2^kk
                    esum -= kk;
                    a0 *= sc; a1r *= sc; a2r *= sc; a3r *= sc; a4r *= sc;
                }
            }
        }
    }

    // loss = -( log(alpha[2Ll] + alpha[2Ll-1]) + esum*ln2 )
    const int se0 = 2 * Ll;
    const int se1 = 2 * Ll - 1;
    const int l0 = se0 / JPER, j0 = se0 % JPER;
    const int l1 = se1 / JPER, j1 = se1 % JPER;

    const float v0 = pick5(a0, a1r, a2r, a3r, a4r, j0);
    const float v1 = pick5(a0, a1r, a2r, a3r, a4r, j1);
    const float fa1 = __shfl_sync(FULL, v0, l0);
    const float fa2 = __shfl_sync(FULL, v1, l1);

    if (lane == 0) {
        const float s = fmaxf(fa1 + fa2, 1e-43f);
        out[b] = -(logf(s) + (float)esum * 0.6931471805599453f);
    }

    cpwait<0>();   // drain stragglers before exit
}

extern "C" void kernel_launch(void* const* d_in, const int* in_sizes, int n_in,
                              void* d_out, int out_size)
{
    const int*   y_true       = (const int*)  d_in[0];   // [B,L] int32
    const float* y_pred       = (const float*)d_in[1];   // [B,T,C] f32
    const int*   input_length = (const int*)  d_in[2];   // [B,1] int32
    const int*   label_length = (const int*)  d_in[3];   // [B,1] int32
    float*       out          = (float*)d_out;           // [B,1] f32

    ctc_fused_kernel<<<BQ, 32>>>(y_true, y_pred, input_length, label_length, out);
}

// round 13
// speedup vs baseline: 1.1298x; 1.0604x over previous
#include <cuda_runtime.h>
#include <cstdint>

// Problem constants (fixed by the dataset)
#define BQ    128
#define TT    512
#define CC    1024
#define LL    64
#define SS    129           // 2*LL + 1 extended states
#define BLANKC 1023
#define EPSF  1e-7f
#define JPER  5             // states per lane (26 lanes * 5 = 130 >= 129)
#define CHUNK 16            // steps per producer/consumer chunk
#define NROWS 64            // smem ring rows = 4 chunks (3 live + slack)
#define RSTRIDE 68          // ring row stride in floats (66 used)
#define EF_TARGET 226       // rescale anchor: warp max near 2^99

__device__ __forceinline__ void cpasync4(uint32_t saddr, const float* g) {
    asm volatile("cp.async.ca.shared.global [%0], [%1], 4;"
                 :: "r"(saddr), "l"(g) : "memory");
}
__device__ __forceinline__ void cpcommit() {
    asm volatile("cp.async.commit_group;" ::: "memory");
}
template <int N> __device__ __forceinline__ void cpwait() {
    asm volatile("cp.async.wait_group %0;" :: "n"(N) : "memory");
}
__device__ __forceinline__ void barsync() {
    asm volatile("barrier.sync 0;" ::: "memory");
}

__device__ __forceinline__ float pick5(const float a0, const float a1, const float a2,
                                       const float a3, const float a4, int j) {
    float r = a0;
    if (j == 1) r = a1;
    else if (j == 2) r = a2;
    else if (j == 3) r = a3;
    else if (j == 4) r = a4;
    return r;
}

__global__ __launch_bounds__(64, 1)
void ctc_pc_kernel(const int* __restrict__ y_true,
                   const float* __restrict__ y_pred,
                   const int* __restrict__ input_length,
                   const int* __restrict__ label_length,
                   float* __restrict__ out)
{
    __shared__ float ring[NROWS][RSTRIDE];

    const int b    = blockIdx.x;
    const int tid  = threadIdx.x;
    const int warp = tid >> 5;
    const int lane = tid & 31;
    const unsigned FULL = 0xffffffffu;

    const int Tb  = input_length[b];         // block-uniform, in [256, 512]
    const int Ll  = label_length[b];
    const int Sb  = 2 * Ll + 1;
    const int NCH = (Tb + CHUNK - 1) / CHUNK;   // >= 16

    const int*   lrow = y_true + b * LL;
    const float* prow = y_pred + (size_t)b * TT * CC;
    const uint32_t smem_base = (uint32_t)__cvta_generic_to_shared(&ring[0][0]);

    if (warp == 1) {
        // ============================ PRODUCER ============================
        const float* g0 = prow + lrow[lane];        // label class lane
        const float* g1 = prow + lrow[lane + 32];   // label class lane+32
        const float* gb = prow + BLANKC;            // blank (lane 0 only)

#define FETCH_CHUNK(ci_) do {                                                        \
            const int base__ = (ci_) * CHUNK;                                        \
            _Pragma("unroll")                                                        \
            for (int q = 0; q < CHUNK; q++) {                                        \
                const int r__ = base__ + q;                                          \
                if (r__ < Tb) {                                                      \
                    const uint32_t wa__ = smem_base                                  \
                        + (uint32_t)(((r__) & (NROWS - 1)) * RSTRIDE + lane) * 4u;   \
                    cpasync4(wa__, g0 + (size_t)r__ * CC);                           \
                    cpasync4(wa__ + 128u, g1 + (size_t)r__ * CC);                    \
                    if (lane == 0)                                                   \
                        cpasync4(smem_base                                           \
                            + (uint32_t)(((r__) & (NROWS - 1)) * RSTRIDE + 64) * 4u, \
                            gb + (size_t)r__ * CC);                                  \
                }                                                                    \
                cpcommit();                                                          \
            }                                                                        \
        } while (0)

        // prologue: chunks 0 and 1 in flight (32 rows), then announce chunk 0
        FETCH_CHUNK(0);
        FETCH_CHUNK(1);
        cpwait<CHUNK>();      // chunk 0 fully landed (16 newest groups may pend)
        barsync();            // bar #1: chunk 0 ready

        for (int i = 2; i < NCH; i++) {
            FETCH_CHUNK(i);
            cpwait<CHUNK>();  // chunk i-1 fully landed
            barsync();        // bar #i: chunk i-1 ready
        }
        cpwait<0>();
        barsync();            // bar #NCH: chunk NCH-1 ready
#undef FETCH_CHUNK
    } else {
        // ============================ CONSUMER ============================
        // zero sink slot 65 of every ring row (producer never writes slot 65;
        // same-warp write->read needs no sync)
        for (int r = lane; r < NROWS; r += 32) ring[r][65] = 0.0f;

        // Per-lane static state metadata: states s = lane*5 + j
        int   off[JPER];     // 0..63 label, 64 blank, 65 zero sink (invalid)
        float skipf[JPER];
#pragma unroll
        for (int j = 0; j < JPER; j++) {
            const int s = lane * JPER + j;
            const bool v = (s < SS) && (s < Sb);
            int  o  = 65;
            bool sk = false;
            if (v) {
                if (s & 1) {
                    o = s >> 1;
                    if (s >= 3) sk = (lrow[o] != lrow[o - 1]);
                } else {
                    o = 64;
                }
            }
            off[j]   = o;
            skipf[j] = sk ? 1.0f : 0.0f;
        }

        // alpha init: linear domain, mass 1 at s=0
        float a0 = 0.f, a1r = 0.f, a2r = 0.f, a3r = 0.f, a4r = 0.f;
        if (lane == 0) a0 = 1.0f;

        int esum = 0;        // exact power-of-two rescale accumulator

        for (int c = 0; c < NCH; c++) {
            barsync();       // chunk c resident (rows 16c .. 16c+15, < Tb)
            const int base = c * CHUNK;

            // emissions for the chunk's first step
            float ee[JPER];
            {
                const float* rr = &ring[base & (NROWS - 1)][0];
#pragma unroll
                for (int j = 0; j < JPER; j++) ee[j] = rr[off[j]] + EPSF;
            }

#pragma unroll
            for (int k = 0; k < CHUNK; k++) {
                const int t = base + k;

                // issue next-row reads early (latency hidden under alpha chain)
                float r0 = 0.f, r1 = 0.f, r2 = 0.f, r3 = 0.f, r4 = 0.f;
                if (k < CHUNK - 1) {
                    const float* rr = &ring[(t + 1) & (NROWS - 1)][0];
                    r0 = rr[off[0]]; r1 = rr[off[1]]; r2 = rr[off[2]];
                    r3 = rr[off[3]]; r4 = rr[off[4]];
                }

                if (t < Tb) {
                    float h3 = __shfl_up_sync(FULL, a3r, 1);
                    float h4 = __shfl_up_sync(FULL, a4r, 1);
                    if (lane == 0) { h3 = 0.f; h4 = 0.f; }

                    const float n0 = (a0  + h4  + skipf[0] * h3 ) * ee[0];
                    const float n1 = (a1r + a0  + skipf[1] * h4 ) * ee[1];
                    const float n2 = (a2r + a1r + skipf[2] * a0 ) * ee[2];
                    const float n3 = (a3r + a2r + skipf[3] * a1r) * ee[3];
                    const float n4 = (a4r + a3r + skipf[4] * a2r) * ee[4];
                    a0 = n0; a1r = n1; a2r = n2; a3r = n3; a4r = n4;
                }

                if (k < CHUNK - 1) {
                    ee[0] = r0 + EPSF; ee[1] = r1 + EPSF; ee[2] = r2 + EPSF;
                    ee[3] = r3 + EPSF; ee[4] = r4 + EPSF;
                }

                // exact power-of-two rescale every 4 steps (anchor ~2^99)
                if ((k & 3) == 3 && t < Tb) {
                    float m = fmaxf(fmaxf(fmaxf(a0, a1r), fmaxf(a2r, a3r)), a4r);
                    unsigned mu = __reduce_max_sync(FULL, __float_as_uint(m));
                    if (mu != 0u) {
                        const int ef = (int)(mu >> 23);
                        int kk = EF_TARGET - ef;
                        kk = kk > 127 ? 127 : (kk < -126 ? -126 : kk);
                        const float sc = __int_as_float((unsigned)(127 + kk) << 23);
                        esum -= kk;
                        a0 *= sc; a1r *= sc; a2r *= sc; a3r *= sc; a4r *= sc;
                    }
                }
            }
        }

        // loss = -( log(alpha[2Ll] + alpha[2Ll-1]) + esum*ln2 )
        const int se0 = 2 * Ll;
        const int se1 = 2 * Ll - 1;
        const int l0 = se0 / JPER, j0 = se0 % JPER;
        const int l1 = se1 / JPER, j1 = se1 % JPER;

        const float v0 = pick5(a0, a1r, a2r, a3r, a4r, j0);
        const float v1 = pick5(a0, a1r, a2r, a3r, a4r, j1);
        const float fa1 = __shfl_sync(FULL, v0, l0);
        const float fa2 = __shfl_sync(FULL, v1, l1);

        if (lane == 0) {
            const float s = fmaxf(fa1 + fa2, 1e-43f);
            out[b] = -(logf(s) + (float)esum * 0.6931471805599453f);
        }
    }
}

extern "C" void kernel_launch(void* const* d_in, const int* in_sizes, int n_in,
                              void* d_out, int out_size)
{
    const int*   y_true       = (const int*)  d_in[0];   // [B,L] int32
    const float* y_pred       = (const float*)d_in[1];   // [B,T,C] f32
    const int*   input_length = (const int*)  d_in[2];   // [B,1] int32
    const int*   label_length = (const int*)  d_in[3];   // [B,1] int32
    float*       out          = (float*)d_out;           // [B,1] f32

    ctc_pc_kernel<<<BQ, 64>>>(y_true, y_pred, input_length, label_length, out);
}